// round 15
// baseline (speedup 1.0000x reference)
#include <cuda_runtime.h>
#include <cuda_bf16.h>
#include <math.h>

#define BSZ 2
#define NSEQ 2048
#define HN 8
#define HD 32
#define EMB 256
#define PDIM 12
#define DIMT 44
#define NRAW 1056
#define CTXW 352
#define NBH 16

typedef unsigned long long u64;
typedef unsigned int u32;

// ---- packed fp32x2 (GEMMs) ----
__device__ __forceinline__ u64 pk2(float lo, float hi) {
    u64 r; asm("mov.b64 %0, {%1, %2};" : "=l"(r) : "f"(lo), "f"(hi)); return r;
}
__device__ __forceinline__ u64 bc2(float x) { return pk2(x, x); }
__device__ __forceinline__ void fma2(u64& d, u64 a, u64 b) {
    asm("fma.rn.f32x2 %0, %1, %2, %0;" : "+l"(d) : "l"(a), "l"(b));
}
__device__ __forceinline__ void upk2(u64 v, float& lo, float& hi) {
    asm("mov.b64 {%0, %1}, %2;" : "=f"(lo), "=f"(hi) : "l"(v));
}

// ---- mma / cp.async / ldmatrix ----
__device__ __forceinline__ u32 smem_u32(const void* p) {
    u32 a; asm("{ .reg .u64 t; cvta.to.shared.u64 t, %1; cvt.u32.u64 %0, t; }" : "=r"(a) : "l"(p));
    return a;
}
__device__ __forceinline__ void mma16816(float* c, const u32* a, u32 b0, u32 b1) {
    asm volatile("mma.sync.aligned.m16n8k16.row.col.f32.bf16.bf16.f32 "
                 "{%0,%1,%2,%3}, {%4,%5,%6,%7}, {%8,%9}, {%0,%1,%2,%3};"
                 : "+f"(c[0]), "+f"(c[1]), "+f"(c[2]), "+f"(c[3])
                 : "r"(a[0]), "r"(a[1]), "r"(a[2]), "r"(a[3]), "r"(b0), "r"(b1));
}
__device__ __forceinline__ void cp16(u32 dst, const void* src) {
    asm volatile("cp.async.cg.shared.global [%0], [%1], 16;" :: "r"(dst), "l"(src));
}
#define CP_COMMIT() asm volatile("cp.async.commit_group;" ::: "memory")
#define CP_WAIT0()  asm volatile("cp.async.wait_group 0;" ::: "memory")
#define CP_WAIT1()  asm volatile("cp.async.wait_group 1;" ::: "memory")
__device__ __forceinline__ void ldsm4(u32& r0, u32& r1, u32& r2, u32& r3, u32 a) {
    asm volatile("ldmatrix.sync.aligned.m8n8.x4.shared.b16 {%0,%1,%2,%3}, [%4];"
                 : "=r"(r0), "=r"(r1), "=r"(r2), "=r"(r3) : "r"(a));
}
__device__ __forceinline__ void ldsm4t(u32& r0, u32& r1, u32& r2, u32& r3, u32 a) {
    asm volatile("ldmatrix.sync.aligned.m8n8.x4.trans.shared.b16 {%0,%1,%2,%3}, [%4];"
                 : "=r"(r0), "=r"(r1), "=r"(r2), "=r"(r3) : "r"(a));
}
__device__ __forceinline__ u32 pkb(float a, float b) {
    __nv_bfloat162 t = __floats2bfloat162_rn(a, b); return *(u32*)&t;
}

// Scratch
__device__ float g_praw[BSZ * NSEQ * NRAW];
__device__ float g_kb[NBH * NSEQ];
__device__ u64 g_mbits[BSZ * NSEQ * (NSEQ / 64)];
__device__ __nv_bfloat16 g_qh[NBH * NSEQ * 64];
__device__ __nv_bfloat16 g_ql[NBH * NSEQ * 64];
__device__ __nv_bfloat16 g_kh[NBH * NSEQ * 64];
__device__ __nv_bfloat16 g_kl[NBH * NSEQ * 64];
__device__ __nv_bfloat16 g_vh[NBH * NSEQ * 64];
__device__ __nv_bfloat16 g_vl[NBH * NSEQ * 64];
__device__ __nv_bfloat16 g_cth[BSZ * NSEQ * CTXW];
__device__ __nv_bfloat16 g_ctl[BSZ * NSEQ * CTXW];
__device__ __nv_bfloat16 g_woh[CTXW * 256];
__device__ __nv_bfloat16 g_wol[CTXW * 256];

// ---------------- proj GEMM (FFMA2, BK=16, register-prefetched) ------------
__device__ __forceinline__
void gemm_body(const float* __restrict__ A, const float* __restrict__ W,
               const float* __restrict__ bias, float* __restrict__ C,
               int K, int Nw, int ldc, int coff, int m0, int n0) {
    __shared__ float As[16][68];
    __shared__ float Bs[16][68];
    const int t = threadIdx.x;
    const int arow = t >> 2, akg = (t & 3) * 4, bk = t >> 4, bn = (t & 15) * 4;
    const int cx = (t & 15) * 4, ry = (t >> 4) * 4;
    u64 acc2[4][2];
#pragma unroll
    for (int i = 0; i < 4; i++) { acc2[i][0] = 0ull; acc2[i][1] = 0ull; }

    float4 a4 = *(const float4*)(A + (size_t)(m0 + arow) * K + akg);
    float4 b4;
    {
        const float* wr = W + (size_t)bk * Nw;
        int gcol = n0 + bn;
        if (gcol + 3 < Nw) b4 = *(const float4*)(wr + gcol);
        else {
            b4.x = (gcol + 0 < Nw) ? wr[gcol + 0] : 0.f;
            b4.y = (gcol + 1 < Nw) ? wr[gcol + 1] : 0.f;
            b4.z = (gcol + 2 < Nw) ? wr[gcol + 2] : 0.f;
            b4.w = (gcol + 3 < Nw) ? wr[gcol + 3] : 0.f;
        }
    }

    for (int k0 = 0; k0 < K; k0 += 16) {
        As[akg + 0][arow] = a4.x; As[akg + 1][arow] = a4.y;
        As[akg + 2][arow] = a4.z; As[akg + 3][arow] = a4.w;
        Bs[bk][bn] = b4.x; Bs[bk][bn + 1] = b4.y;
        Bs[bk][bn + 2] = b4.z; Bs[bk][bn + 3] = b4.w;
        __syncthreads();
        if (k0 + 16 < K) {
            a4 = *(const float4*)(A + (size_t)(m0 + arow) * K + k0 + 16 + akg);
            const float* wr = W + (size_t)(k0 + 16 + bk) * Nw;
            int gcol = n0 + bn;
            if (gcol + 3 < Nw) b4 = *(const float4*)(wr + gcol);
            else {
                b4.x = (gcol + 0 < Nw) ? wr[gcol + 0] : 0.f;
                b4.y = (gcol + 1 < Nw) ? wr[gcol + 1] : 0.f;
                b4.z = (gcol + 2 < Nw) ? wr[gcol + 2] : 0.f;
                b4.w = (gcol + 3 < Nw) ? wr[gcol + 3] : 0.f;
            }
        }
#pragma unroll
        for (int kk = 0; kk < 16; kk++) {
            float4 av = *(const float4*)&As[kk][ry];
            ulonglong2 bv = *(const ulonglong2*)&Bs[kk][cx];
            u64 a0 = bc2(av.x), a1 = bc2(av.y), a2 = bc2(av.z), a3 = bc2(av.w);
            fma2(acc2[0][0], a0, bv.x); fma2(acc2[0][1], a0, bv.y);
            fma2(acc2[1][0], a1, bv.x); fma2(acc2[1][1], a1, bv.y);
            fma2(acc2[2][0], a2, bv.x); fma2(acc2[2][1], a2, bv.y);
            fma2(acc2[3][0], a3, bv.x); fma2(acc2[3][1], a3, bv.y);
        }
        __syncthreads();
    }
#pragma unroll
    for (int i = 0; i < 4; i++) {
        float c0, c1, c2, c3;
        upk2(acc2[i][0], c0, c1); upk2(acc2[i][1], c2, c3);
        float cc[4] = {c0, c1, c2, c3};
        float* crow = C + (size_t)(m0 + ry + i) * ldc + coff;
#pragma unroll
        for (int j = 0; j < 4; j++) { int col = n0 + cx + j; if (col < Nw) crow[col] = cc[j] + bias[col]; }
    }
}

struct ProjArgs { const float* W[6]; const float* bias[6]; };

__global__ __launch_bounds__(256)
void proj_kernel(const float* __restrict__ A, ProjArgs pa, float* __restrict__ C) {
    const int bx = blockIdx.x;
    int g, n0;
    if (bx < 12) { g = bx >> 2; n0 = (bx & 3) * 64; }
    else { g = 3 + ((bx - 12) >> 1); n0 = ((bx - 12) & 1) * 64; }
    const int nw = (g < 3) ? 256 : 96;
    const int coff = (g < 3) ? g * 256 : 768 + (g - 3) * 96;
    gemm_body(A, pa.W[g], pa.bias[g], C, EMB, nw, NRAW, coff, blockIdx.y * 64, n0);
}

__global__ void prep_wo(const float* __restrict__ Wo) {
    int i = blockIdx.x * 256 + threadIdx.x;
    if (i < CTXW * 256) {
        float w = Wo[i];
        __nv_bfloat16 h = __float2bfloat16(w);
        g_woh[i] = h;
        g_wol[i] = __float2bfloat16(w - __bfloat162float(h));
    }
}

// ---------------- mask bit-pack ----------------
__global__ __launch_bounds__(256)
void pack_mask(const unsigned char* __restrict__ mask) {
    int idx = blockIdx.x * 256 + threadIdx.x;
    if (idx >= BSZ * NSEQ * (NSEQ / 64)) return;
    const u64* src = (const u64*)mask + (size_t)idx * 8;
    u64 bits = 0;
#pragma unroll
    for (int g = 0; g < 8; g++) {
        u64 v = src[g];
#pragma unroll
        for (int by = 0; by < 8; by++)
            if ((v >> (8 * by)) & 0xFFull) bits |= 1ull << (g * 8 + by);
    }
    g_mbits[idx] = bits;
}

// ---------------- Transform ----------------
__device__ __forceinline__ float softplusf(float x) { return (x > 20.f) ? x : log1pf(expf(x)); }

__global__ __launch_bounds__(128)
void transform_kernel(const float* __restrict__ coords, const float* __restrict__ w_c,
                      const float* __restrict__ w_l) {
    __shared__ float row[NRAW];
    __shared__ float c3[3];
    __shared__ float wl[HN], wc[HN];
    const int blk = blockIdx.x, b = blk >> 11, pos = blk & (NSEQ - 1);
    const int t = threadIdx.x;
    for (int i = t; i < NRAW; i += 128) row[i] = g_praw[(size_t)blk * NRAW + i];
    if (t < 3) c3[t] = coords[(size_t)blk * 3 + t];
    if (t < HN) { wl[t] = softplusf(w_l[t]); wc[t] = softplusf(w_c[t]); }
    __syncthreads();

    if (t < HN) {
        float s = 0.f;
#pragma unroll
        for (int e = 0; e < PDIM; e++) {
            float v = row[864 + t * PDIM + e] + c3[e % 3];
            s = fmaf(v, v, s);
        }
        g_kb[((size_t)(b * HN + t)) * NSEQ + pos] = -0.5f * wc[t] * s;
    }

    const float RS32 = 0.17677669529663688f;
    for (int idx = t; idx < HN * 48; idx += 128) {
        int h = idx / 48, d = idx % 48;
        float qv = 0.f, kv = 0.f, vv = 0.f;
        if (d < HD) {
            qv = row[h * HD + d] * (wl[h] * RS32);
            kv = row[256 + h * HD + d];
            vv = row[512 + h * HD + d];
        } else if (d < DIMT) {
            int e = d - HD;
            float cc = c3[e % 3];
            qv = (row[768 + h * PDIM + e] + cc) * wc[h];
            kv = row[864 + h * PDIM + e] + cc;
            vv = row[960 + h * PDIM + e] + cc;
        }
        int bh = b * HN + h;
        size_t o = ((size_t)bh * NSEQ + pos) * 64 + d;
        __nv_bfloat16 qh = __float2bfloat16(qv);
        __nv_bfloat16 kh = __float2bfloat16(kv);
        __nv_bfloat16 vh = __float2bfloat16(vv);
        g_qh[o] = qh; g_ql[o] = __float2bfloat16(qv - __bfloat162float(qh));
        g_kh[o] = kh; g_kl[o] = __float2bfloat16(kv - __bfloat162float(kh));
        g_vh[o] = vh; g_vl[o] = __float2bfloat16(vv - __bfloat162float(vh));
    }
}

// ---------------- FA2 mma.sync flash attention (2-stage, ldsm4t V) ---------
#define BUF_SZ 28672
#define OFF_K  0
#define OFF_KL 7168
#define OFF_VT 14336
#define SB_RED 57344
#define SB_TOT 58368

template<bool MASKED>
__device__ __forceinline__ void attn_tile(
    u32 kls, u32 vth, u32 vtl, const float* __restrict__ kbj, u64 mb0, u64 mb1, int tig,
    const u32 (*__restrict__ qfh)[4], const u32 (*__restrict__ qfl)[4],
    float (*__restrict__ oc)[4], float& la, float& lb,
    float& m0a, float& m0b, bool init)
{
#pragma unroll
    for (int kj = 0; kj < 4; kj++) {
        const int nb0 = 2 * kj, nb1 = 2 * kj + 1;
        float sc0[4] = {0.f, 0.f, 0.f, 0.f};
        float sc1[4] = {0.f, 0.f, 0.f, 0.f};
#pragma unroll
        for (int ks = 0; ks < 3; ks++) {
            u32 a0, a1, a2, a3;
            ldsm4(a0, a1, a2, a3, kls + nb0 * 896 + ks * 32);
            mma16816(sc0, qfh[ks], a0, a1);
            mma16816(sc0, qfh[ks], a2, a3);
            mma16816(sc0, qfl[ks], a0, a1);
            u32 b0, b1, b2, b3;
            ldsm4(b0, b1, b2, b3, kls + nb1 * 896 + ks * 32);
            mma16816(sc1, qfh[ks], b0, b1);
            mma16816(sc1, qfh[ks], b2, b3);
            mma16816(sc1, qfl[ks], b0, b1);
        }
        {
            float2 kba = *(const float2*)(kbj + nb0 * 8 + 2 * tig);
            float2 kbb = *(const float2*)(kbj + nb1 * 8 + 2 * tig);
            sc0[0] += kba.x; sc0[1] += kba.y; sc0[2] += kba.x; sc0[3] += kba.y;
            sc1[0] += kbb.x; sc1[1] += kbb.y; sc1[2] += kbb.x; sc1[3] += kbb.y;
            if (MASKED) {
                int sh0 = nb0 * 8 + 2 * tig, sh1 = nb1 * 8 + 2 * tig;
                if ((mb0 >> sh0) & 1) sc0[0] = -INFINITY;
                if ((mb0 >> (sh0 + 1)) & 1) sc0[1] = -INFINITY;
                if ((mb1 >> sh0) & 1) sc0[2] = -INFINITY;
                if ((mb1 >> (sh0 + 1)) & 1) sc0[3] = -INFINITY;
                if ((mb0 >> sh1) & 1) sc1[0] = -INFINITY;
                if ((mb0 >> (sh1 + 1)) & 1) sc1[1] = -INFINITY;
                if ((mb1 >> sh1) & 1) sc1[2] = -INFINITY;
                if ((mb1 >> (sh1 + 1)) & 1) sc1[3] = -INFINITY;
            }
        }
        if (init && kj == 0) {
            float ma = fmaxf(fmaxf(sc0[0], sc0[1]), fmaxf(sc1[0], sc1[1]));
            float mb = fmaxf(fmaxf(sc0[2], sc0[3]), fmaxf(sc1[2], sc1[3]));
            ma = fmaxf(ma, __shfl_xor_sync(0xffffffffu, ma, 1));
            ma = fmaxf(ma, __shfl_xor_sync(0xffffffffu, ma, 2));
            mb = fmaxf(mb, __shfl_xor_sync(0xffffffffu, mb, 1));
            mb = fmaxf(mb, __shfl_xor_sync(0xffffffffu, mb, 2));
            m0a = fmaxf(ma, -1e4f) + 2.f;
            m0b = fmaxf(mb, -1e4f) + 2.f;
        }
        float p0 = __expf(sc0[0] - m0a), p1 = __expf(sc0[1] - m0a);
        float p2 = __expf(sc0[2] - m0b), p3 = __expf(sc0[3] - m0b);
        float p4 = __expf(sc1[0] - m0a), p5 = __expf(sc1[1] - m0a);
        float p6 = __expf(sc1[2] - m0b), p7 = __expf(sc1[3] - m0b);
        la += (p0 + p1) + (p4 + p5);
        lb += (p2 + p3) + (p6 + p7);
        u32 u0 = __float_as_uint(p0), u1 = __float_as_uint(p1);
        u32 u2 = __float_as_uint(p2), u3 = __float_as_uint(p3);
        u32 u4 = __float_as_uint(p4), u5 = __float_as_uint(p5);
        u32 u6 = __float_as_uint(p6), u7 = __float_as_uint(p7);
        u32 pha[4], pla[4];
        pha[0] = __byte_perm(u0, u1, 0x7632);
        pha[1] = __byte_perm(u2, u3, 0x7632);
        pha[2] = __byte_perm(u4, u5, 0x7632);
        pha[3] = __byte_perm(u6, u7, 0x7632);
        pla[0] = pkb(p0 - __uint_as_float(u0 & 0xFFFF0000u), p1 - __uint_as_float(u1 & 0xFFFF0000u));
        pla[1] = pkb(p2 - __uint_as_float(u2 & 0xFFFF0000u), p3 - __uint_as_float(u3 & 0xFFFF0000u));
        pla[2] = pkb(p4 - __uint_as_float(u4 & 0xFFFF0000u), p5 - __uint_as_float(u5 & 0xFFFF0000u));
        pla[3] = pkb(p6 - __uint_as_float(u6 & 0xFFFF0000u), p7 - __uint_as_float(u7 & 0xFFFF0000u));
#pragma unroll
        for (int ctp = 0; ctp < 3; ctp++) {
            u32 vh0, vh1, vh2, vh3, vl0, vl1, vl2, vl3;
            ldsm4t(vh0, vh1, vh2, vh3, vth + kj * 1792 + ctp * 32);
            ldsm4t(vl0, vl1, vl2, vl3, vtl + kj * 1792 + ctp * 32);
            mma16816(oc[2 * ctp], pha, vh0, vh1);
            mma16816(oc[2 * ctp], pha, vl0, vl1);
            mma16816(oc[2 * ctp], pla, vh0, vh1);
            mma16816(oc[2 * ctp + 1], pha, vh2, vh3);
            mma16816(oc[2 * ctp + 1], pha, vl2, vl3);
            mma16816(oc[2 * ctp + 1], pla, vh2, vh3);
        }
    }
}

__global__ __launch_bounds__(256, 2)
void attn_kernel() {
    extern __shared__ char smem[];
    const u32 sb = smem_u32(smem);
    const int t = threadIdx.x;
    const int w = t >> 5, lane = t & 31;
    const int gid = lane >> 2, tig = lane & 3;
    const int rb = w * 16;
    const int i0 = blockIdx.x * 128, h = blockIdx.y, b = blockIdx.z;
    const int bh = b * HN + h;
    const float* kbg = g_kb + (size_t)bh * NSEQ;

    const int mid = lane >> 3, r8 = lane & 7;
    const u32 klbase = sb + ((mid < 2) ? OFF_K : OFF_KL) + r8 * 112 + (mid & 1) * 16;
    const u32 vtbase = sb + OFF_VT + (u32)(((mid & 1) * 8 + r8) * 112 + (mid >> 1) * 16);

#define KV_ISSUE(jn, nb_base) do {                                                                 \
        _Pragma("unroll")                                                                          \
        for (int rep = 0; rep < 3; rep++) {                                                        \
            int i = t + rep * 256;                                                                 \
            int arr = i / 384, rem = i % 384;                                                      \
            int row_ = rem / 6, ch = rem % 6;                                                      \
            size_t gb = ((size_t)bh * NSEQ + (jn) + row_) << 7;                                    \
            cp16((nb_base) + OFF_K + arr * 7168 + row_ * 112 + ch * 16,                            \
                 (const char*)(arr ? g_kl : g_kh) + gb + ch * 16);                                 \
            cp16((nb_base) + OFF_VT + arr * 7168 + row_ * 112 + ch * 16,                           \
                 (const char*)(arr ? g_vl : g_vh) + gb + ch * 16);                                 \
        }                                                                                          \
    } while (0)

    KV_ISSUE(0, sb);
    CP_COMMIT();

    {
        int arr = t >> 7, r = t & 127;
        const uint4* src = (const uint4*)((arr ? g_ql : g_qh) + ((size_t)bh * NSEQ + i0 + r) * 64);
        char* dst = smem + BUF_SZ + arr * 12288 + r * 96;
#pragma unroll
        for (int g = 0; g < 6; g++) *(uint4*)(dst + g * 16) = src[g];
    }
    __syncthreads();

    u32 qfh[3][4], qfl[3][4];
    {
        const char* Qb = smem + BUF_SZ;
#pragma unroll
        for (int ks = 0; ks < 3; ks++) {
            int co = ks * 32 + 4 * tig;
            int r0 = (rb + gid) * 96, r1 = (rb + gid + 8) * 96;
            qfh[ks][0] = *(const u32*)(Qb + r0 + co);
            qfh[ks][1] = *(const u32*)(Qb + r1 + co);
            qfh[ks][2] = *(const u32*)(Qb + r0 + co + 16);
            qfh[ks][3] = *(const u32*)(Qb + r1 + co + 16);
            qfl[ks][0] = *(const u32*)(Qb + 12288 + r0 + co);
            qfl[ks][1] = *(const u32*)(Qb + 12288 + r1 + co);
            qfl[ks][2] = *(const u32*)(Qb + 12288 + r0 + co + 16);
            qfl[ks][3] = *(const u32*)(Qb + 12288 + r1 + co + 16);
        }
    }

    float oc[6][4];
#pragma unroll
    for (int ct = 0; ct < 6; ct++)
#pragma unroll
        for (int i = 0; i < 4; i++) oc[ct][i] = 0.f;

    float la = 0.f, lb = 0.f, m0a = 0.f, m0b = 0.f;
    const u64* mb0p = g_mbits + ((size_t)(b * NSEQ + i0 + rb + gid)) * (NSEQ / 64);
    const u64* mb1p = mb0p + 8 * (NSEQ / 64);

    for (int tt = 0; tt < 32; tt++) {
        const int j0 = tt * 64;
        const u64 mb0 = mb0p[tt], mb1 = mb1p[tt];
        CP_WAIT0();
        __syncthreads();
        if (tt + 1 < 32) {
            KV_ISSUE(j0 + 64, sb + ((tt + 1) & 1) * BUF_SZ);
            CP_COMMIT();
        }
        const u32 kls = klbase + (tt & 1) * BUF_SZ;
        const u32 vth = vtbase + (tt & 1) * BUF_SZ;
        const u32 vtl = vth + 7168;

        if ((mb0 | mb1) == 0ull)
            attn_tile<false>(kls, vth, vtl, kbg + j0, mb0, mb1, tig, qfh, qfl,
                             oc, la, lb, m0a, m0b, tt == 0);
        else
            attn_tile<true>(kls, vth, vtl, kbg + j0, mb0, mb1, tig, qfh, qfl,
                            oc, la, lb, m0a, m0b, tt == 0);
    }

    // ---- epilogue: write ctx as bf16 hi/lo ----
    la += __shfl_xor_sync(0xffffffffu, la, 1);
    la += __shfl_xor_sync(0xffffffffu, la, 2);
    lb += __shfl_xor_sync(0xffffffffu, lb, 1);
    lb += __shfl_xor_sync(0xffffffffu, lb, 2);
    float* red = (float*)(smem + SB_RED);
    float* Es = (float*)smem;
#pragma unroll
    for (int ct = 0; ct < 6; ct++) {
        *(float2*)&Es[(rb + gid) * 50 + ct * 8 + 2 * tig] = make_float2(oc[ct][0], oc[ct][1]);
        *(float2*)&Es[(rb + gid + 8) * 50 + ct * 8 + 2 * tig] = make_float2(oc[ct][2], oc[ct][3]);
    }
    if (tig == 0) { red[rb + gid] = la; red[rb + gid + 8] = lb; }
    __syncthreads();

    int row = t >> 1, half = t & 1;
    float inv = 1.f / red[row];
    size_t ob = ((size_t)b * NSEQ + i0 + row) * CTXW;
    const float* orow = Es + row * 50;
    const int cbeg = half ? 24 : 0, cend = half ? 44 : 24;
    for (int c = cbeg; c < cend; c++) {
        float o = orow[c] * inv;
        int col = (c < HD) ? h * HD + c : 256 + h * PDIM + (c - HD);
        __nv_bfloat16 oh = __float2bfloat16(o);
        g_cth[ob + col] = oh;
        g_ctl[ob + col] = __float2bfloat16(o - __bfloat162float(oh));
    }
#undef KV_ISSUE
}

// ---------------- tensor-core output GEMM (3-stage pipeline) ----------------
// out[4096,256] = cth/ctl @ woh/wol + bo ; CTA 128x64, K=352 (22x16)
#define OG_A   0
#define OG_AL  4096
#define OG_B   8192
#define OG_BL  10240
#define OG_BUF 12288

__global__ __launch_bounds__(256)
void out_gemm(const float* __restrict__ bo, float* __restrict__ out) {
    __shared__ char smem[3 * OG_BUF];
    const u32 sb = smem_u32(smem);
    const int t = threadIdx.x, w = t >> 5, lane = t & 31;
    const int gid = lane >> 2, tig = lane & 3;
    const int m0 = blockIdx.y * 128, n0 = blockIdx.x * 64;
    const int rb = w * 16;

    const int sr = t >> 1, sc_ = t & 1;
    const int br = (t & 127) >> 3, bc = t & 7;

    float oc[8][4];
#pragma unroll
    for (int nb = 0; nb < 8; nb++)
#pragma unroll
        for (int i = 0; i < 4; i++) oc[nb][i] = 0.f;

#define OG_ISSUE(kc, bufb) do {                                                    \
        int k0 = (kc) * 16;                                                        \
        cp16((bufb) + OG_A + sr * 32 + sc_ * 16,                                   \
             (const char*)(g_cth + (size_t)(m0 + sr) * CTXW + k0) + sc_ * 16);     \
        cp16((bufb) + OG_AL + sr * 32 + sc_ * 16,                                  \
             (const char*)(g_ctl + (size_t)(m0 + sr) * CTXW + k0) + sc_ * 16);     \
        const __nv_bfloat16* Wp = (t < 128) ? g_woh : g_wol;                       \
        cp16((bufb) + ((t < 128) ? OG_B : OG_BL) + br * 128 + bc * 16,             \
             (const char*)(Wp + (size_t)(k0 + br) * 256 + n0) + bc * 16);          \
    } while (0)

    OG_ISSUE(0, sb); CP_COMMIT();
    OG_ISSUE(1, sb + OG_BUF); CP_COMMIT();

    const u32 aoff = (u32)((lane & 15) * 32 + (lane >> 4) * 16);
    const u32 boff = (u32)((lane & 15) * 128 + (lane >> 4) * 16);

    for (int kc = 0; kc < 22; kc++) {
        u32 bufb = sb + (kc % 3) * OG_BUF;
        CP_WAIT1();
        __syncthreads();
        {
            int nk = kc + 2;
            if (nk < 22) OG_ISSUE(nk, sb + (nk % 3) * OG_BUF);
            CP_COMMIT();
        }

        u32 ah[4], al[4];
        ldsm4(ah[0], ah[1], ah[2], ah[3], bufb + OG_A + rb * 32 + aoff);
        ldsm4(al[0], al[1], al[2], al[3], bufb + OG_AL + rb * 32 + aoff);
#pragma unroll
        for (int np = 0; np < 4; np++) {
            u32 bh0, bh1, bh2, bh3, bl0, bl1, bl2, bl3;
            ldsm4t(bh0, bh1, bh2, bh3, bufb + OG_B + boff + np * 32);
            ldsm4t(bl0, bl1, bl2, bl3, bufb + OG_BL + boff + np * 32);
            mma16816(oc[2 * np], ah, bh0, bh1);
            mma16816(oc[2 * np], ah, bl0, bl1);
            mma16816(oc[2 * np], al, bh0, bh1);
            mma16816(oc[2 * np + 1], ah, bh2, bh3);
            mma16816(oc[2 * np + 1], ah, bl2, bl3);
            mma16816(oc[2 * np + 1], al, bh2, bh3);
        }
    }

#pragma unroll
    for (int nb = 0; nb < 8; nb++) {
        int col = n0 + nb * 8 + 2 * tig;
        float2 b2 = *(const float2*)(bo + col);
        *(float2*)(out + (size_t)(m0 + rb + gid) * 256 + col) =
            make_float2(oc[nb][0] + b2.x, oc[nb][1] + b2.y);
        *(float2*)(out + (size_t)(m0 + rb + gid + 8) * 256 + col) =
            make_float2(oc[nb][2] + b2.x, oc[nb][3] + b2.y);
    }
#undef OG_ISSUE
}

// ---------------------------------------------------------------------------
extern "C" void kernel_launch(void* const* d_in, const int* in_sizes, int n_in,
                              void* d_out, int out_size) {
    const float* feat = (const float*)d_in[0];
    const float* coords = (const float*)d_in[1];
    const unsigned char* mask = (const unsigned char*)d_in[2];
    const float* Wo = (const float*)d_in[15];
    const float* bo = (const float*)d_in[16];
    float* out = (float*)d_out;

    void* p;
    cudaGetSymbolAddress(&p, g_praw); float* praw = (float*)p;

    const int M = BSZ * NSEQ;
    ProjArgs pa;
    pa.W[0] = (const float*)d_in[3];  pa.bias[0] = (const float*)d_in[4];
    pa.W[1] = (const float*)d_in[5];  pa.bias[1] = (const float*)d_in[6];
    pa.W[2] = (const float*)d_in[7];  pa.bias[2] = (const float*)d_in[8];
    pa.W[3] = (const float*)d_in[9];  pa.bias[3] = (const float*)d_in[10];
    pa.W[4] = (const float*)d_in[11]; pa.bias[4] = (const float*)d_in[12];
    pa.W[5] = (const float*)d_in[13]; pa.bias[5] = (const float*)d_in[14];
    proj_kernel<<<dim3(18, M / 64), 256>>>(feat, pa, praw);

    prep_wo<<<(CTXW * 256 + 255) / 256, 256>>>(Wo);
    pack_mask<<<(BSZ * NSEQ * (NSEQ / 64) + 255) / 256, 256>>>(mask);
    transform_kernel<<<M, 128>>>(coords, (const float*)d_in[17], (const float*)d_in[18]);

    cudaFuncSetAttribute(attn_kernel, cudaFuncAttributeMaxDynamicSharedMemorySize, SB_TOT);
    attn_kernel<<<dim3(16, HN, BSZ), 256, SB_TOT>>>();

    out_gemm<<<dim3(4, M / 128), 256>>>(bo, out);
}

// round 16
// speedup vs baseline: 1.0974x; 1.0974x over previous
#include <cuda_runtime.h>
#include <cuda_bf16.h>
#include <math.h>

#define BSZ 2
#define NSEQ 2048
#define HN 8
#define HD 32
#define EMB 256
#define PDIM 12
#define DIMT 44
#define NRAW 1056
#define CTXW 352
#define NBH 16

typedef unsigned long long u64;
typedef unsigned int u32;

// ---- packed fp32x2 (GEMMs) ----
__device__ __forceinline__ u64 pk2(float lo, float hi) {
    u64 r; asm("mov.b64 %0, {%1, %2};" : "=l"(r) : "f"(lo), "f"(hi)); return r;
}
__device__ __forceinline__ u64 bc2(float x) { return pk2(x, x); }
__device__ __forceinline__ void fma2(u64& d, u64 a, u64 b) {
    asm("fma.rn.f32x2 %0, %1, %2, %0;" : "+l"(d) : "l"(a), "l"(b));
}
__device__ __forceinline__ void upk2(u64 v, float& lo, float& hi) {
    asm("mov.b64 {%0, %1}, %2;" : "=f"(lo), "=f"(hi) : "l"(v));
}

// ---- mma / cp.async / ldmatrix ----
__device__ __forceinline__ u32 smem_u32(const void* p) {
    u32 a; asm("{ .reg .u64 t; cvta.to.shared.u64 t, %1; cvt.u32.u64 %0, t; }" : "=r"(a) : "l"(p));
    return a;
}
__device__ __forceinline__ void mma16816(float* c, const u32* a, u32 b0, u32 b1) {
    asm volatile("mma.sync.aligned.m16n8k16.row.col.f32.bf16.bf16.f32 "
                 "{%0,%1,%2,%3}, {%4,%5,%6,%7}, {%8,%9}, {%0,%1,%2,%3};"
                 : "+f"(c[0]), "+f"(c[1]), "+f"(c[2]), "+f"(c[3])
                 : "r"(a[0]), "r"(a[1]), "r"(a[2]), "r"(a[3]), "r"(b0), "r"(b1));
}
__device__ __forceinline__ void cp16(u32 dst, const void* src) {
    asm volatile("cp.async.cg.shared.global [%0], [%1], 16;" :: "r"(dst), "l"(src));
}
#define CP_COMMIT() asm volatile("cp.async.commit_group;" ::: "memory")
#define CP_WAIT0()  asm volatile("cp.async.wait_group 0;" ::: "memory")
__device__ __forceinline__ void ldsm4(u32& r0, u32& r1, u32& r2, u32& r3, u32 a) {
    asm volatile("ldmatrix.sync.aligned.m8n8.x4.shared.b16 {%0,%1,%2,%3}, [%4];"
                 : "=r"(r0), "=r"(r1), "=r"(r2), "=r"(r3) : "r"(a));
}
__device__ __forceinline__ void ldsm4t(u32& r0, u32& r1, u32& r2, u32& r3, u32 a) {
    asm volatile("ldmatrix.sync.aligned.m8n8.x4.trans.shared.b16 {%0,%1,%2,%3}, [%4];"
                 : "=r"(r0), "=r"(r1), "=r"(r2), "=r"(r3) : "r"(a));
}
__device__ __forceinline__ u32 pkb(float a, float b) {
    __nv_bfloat162 t = __floats2bfloat162_rn(a, b); return *(u32*)&t;
}

// Scratch
__device__ float g_praw[BSZ * NSEQ * NRAW];
__device__ float g_kb[NBH * NSEQ];
__device__ float g_ctx[BSZ * NSEQ * CTXW];
__device__ u64 g_mbits[BSZ * NSEQ * (NSEQ / 64)];
__device__ __nv_bfloat16 g_qh[NBH * NSEQ * 64];
__device__ __nv_bfloat16 g_ql[NBH * NSEQ * 64];
__device__ __nv_bfloat16 g_kh[NBH * NSEQ * 64];
__device__ __nv_bfloat16 g_kl[NBH * NSEQ * 64];
__device__ __nv_bfloat16 g_vh[NBH * NSEQ * 64];
__device__ __nv_bfloat16 g_vl[NBH * NSEQ * 64];

// ---------------- GEMM (FFMA2, BK=16, register-prefetched) ----------------
__device__ __forceinline__
void gemm_body(const float* __restrict__ A, const float* __restrict__ W,
               const float* __restrict__ bias, float* __restrict__ C,
               int K, int Nw, int ldc, int coff, int m0, int n0) {
    __shared__ float As[16][68];
    __shared__ float Bs[16][68];
    const int t = threadIdx.x;
    const int arow = t >> 2, akg = (t & 3) * 4, bk = t >> 4, bn = (t & 15) * 4;
    const int cx = (t & 15) * 4, ry = (t >> 4) * 4;
    u64 acc2[4][2];
#pragma unroll
    for (int i = 0; i < 4; i++) { acc2[i][0] = 0ull; acc2[i][1] = 0ull; }

    float4 a4 = *(const float4*)(A + (size_t)(m0 + arow) * K + akg);
    float4 b4;
    {
        const float* wr = W + (size_t)bk * Nw;
        int gcol = n0 + bn;
        if (gcol + 3 < Nw) b4 = *(const float4*)(wr + gcol);
        else {
            b4.x = (gcol + 0 < Nw) ? wr[gcol + 0] : 0.f;
            b4.y = (gcol + 1 < Nw) ? wr[gcol + 1] : 0.f;
            b4.z = (gcol + 2 < Nw) ? wr[gcol + 2] : 0.f;
            b4.w = (gcol + 3 < Nw) ? wr[gcol + 3] : 0.f;
        }
    }

    for (int k0 = 0; k0 < K; k0 += 16) {
        As[akg + 0][arow] = a4.x; As[akg + 1][arow] = a4.y;
        As[akg + 2][arow] = a4.z; As[akg + 3][arow] = a4.w;
        Bs[bk][bn] = b4.x; Bs[bk][bn + 1] = b4.y;
        Bs[bk][bn + 2] = b4.z; Bs[bk][bn + 3] = b4.w;
        __syncthreads();
        if (k0 + 16 < K) {
            a4 = *(const float4*)(A + (size_t)(m0 + arow) * K + k0 + 16 + akg);
            const float* wr = W + (size_t)(k0 + 16 + bk) * Nw;
            int gcol = n0 + bn;
            if (gcol + 3 < Nw) b4 = *(const float4*)(wr + gcol);
            else {
                b4.x = (gcol + 0 < Nw) ? wr[gcol + 0] : 0.f;
                b4.y = (gcol + 1 < Nw) ? wr[gcol + 1] : 0.f;
                b4.z = (gcol + 2 < Nw) ? wr[gcol + 2] : 0.f;
                b4.w = (gcol + 3 < Nw) ? wr[gcol + 3] : 0.f;
            }
        }
#pragma unroll
        for (int kk = 0; kk < 16; kk++) {
            float4 av = *(const float4*)&As[kk][ry];
            ulonglong2 bv = *(const ulonglong2*)&Bs[kk][cx];
            u64 a0 = bc2(av.x), a1 = bc2(av.y), a2 = bc2(av.z), a3 = bc2(av.w);
            fma2(acc2[0][0], a0, bv.x); fma2(acc2[0][1], a0, bv.y);
            fma2(acc2[1][0], a1, bv.x); fma2(acc2[1][1], a1, bv.y);
            fma2(acc2[2][0], a2, bv.x); fma2(acc2[2][1], a2, bv.y);
            fma2(acc2[3][0], a3, bv.x); fma2(acc2[3][1], a3, bv.y);
        }
        __syncthreads();
    }
#pragma unroll
    for (int i = 0; i < 4; i++) {
        float c0, c1, c2, c3;
        upk2(acc2[i][0], c0, c1); upk2(acc2[i][1], c2, c3);
        float cc[4] = {c0, c1, c2, c3};
        float* crow = C + (size_t)(m0 + ry + i) * ldc + coff;
#pragma unroll
        for (int j = 0; j < 4; j++) { int col = n0 + cx + j; if (col < Nw) crow[col] = cc[j] + bias[col]; }
    }
}

struct ProjArgs { const float* W[6]; const float* bias[6]; };

__global__ __launch_bounds__(256)
void proj_kernel(const float* __restrict__ A, ProjArgs pa, float* __restrict__ C) {
    const int bx = blockIdx.x;
    int g, n0;
    if (bx < 12) { g = bx >> 2; n0 = (bx & 3) * 64; }
    else { g = 3 + ((bx - 12) >> 1); n0 = ((bx - 12) & 1) * 64; }
    const int nw = (g < 3) ? 256 : 96;
    const int coff = (g < 3) ? g * 256 : 768 + (g - 3) * 96;
    gemm_body(A, pa.W[g], pa.bias[g], C, EMB, nw, NRAW, coff, blockIdx.y * 64, n0);
}

__global__ __launch_bounds__(256)
void gemm_kernel(const float* __restrict__ A, const float* __restrict__ W,
                 const float* __restrict__ bias, float* __restrict__ C, int K, int Nw, int ldc) {
    gemm_body(A, W, bias, C, K, Nw, ldc, 0, blockIdx.y * 64, blockIdx.x * 64);
}

// ---------------- mask bit-pack (movemask trick) ----------------
__global__ __launch_bounds__(256)
void pack_mask(const unsigned char* __restrict__ mask) {
    int idx = blockIdx.x * 256 + threadIdx.x;
    if (idx >= BSZ * NSEQ * (NSEQ / 64)) return;
    const u64* src = (const u64*)mask + (size_t)idx * 8;
    u64 bits = 0;
#pragma unroll
    for (int g = 0; g < 8; g++) {
        u64 v = src[g];
        v |= v >> 4; v |= v >> 2; v |= v >> 1;           // byte-nonzero -> LSB
        u64 m = ((v & 0x0101010101010101ull) * 0x0102040810204080ull) >> 56;
        bits |= m << (8 * g);
    }
    g_mbits[idx] = bits;
}

// ---------------- Transform (2-wide vectorized) ----------------
__device__ __forceinline__ float softplusf(float x) { return (x > 20.f) ? x : log1pf(expf(x)); }

__global__ __launch_bounds__(128)
void transform_kernel(const float* __restrict__ coords, const float* __restrict__ w_c,
                      const float* __restrict__ w_l) {
    __shared__ float row[NRAW];
    __shared__ float c3[3];
    __shared__ float wl[HN], wc[HN];
    const int blk = blockIdx.x, b = blk >> 11, pos = blk & (NSEQ - 1);
    const int t = threadIdx.x;
    {
        const float4* src = (const float4*)(g_praw + (size_t)blk * NRAW);
        float4* dst = (float4*)row;
        for (int i = t; i < NRAW / 4; i += 128) dst[i] = src[i];
    }
    if (t < 3) c3[t] = coords[(size_t)blk * 3 + t];
    if (t < HN) { wl[t] = softplusf(w_l[t]); wc[t] = softplusf(w_c[t]); }
    __syncthreads();

    if (t < HN) {
        float s = 0.f;
#pragma unroll
        for (int e = 0; e < PDIM; e++) {
            float v = row[864 + t * PDIM + e] + c3[e % 3];
            s = fmaf(v, v, s);
        }
        g_kb[((size_t)(b * HN + t)) * NSEQ + pos] = -0.5f * wc[t] * s;
    }

    const float RS32 = 0.17677669529663688f;
    for (int idx = t; idx < HN * 24; idx += 128) {
        int h = idx / 24, d0 = (idx % 24) * 2;
        float q2[2], k2[2], v2[2];
#pragma unroll
        for (int u = 0; u < 2; u++) {
            int d = d0 + u;
            float qv = 0.f, kv = 0.f, vv = 0.f;
            if (d < HD) {
                qv = row[h * HD + d] * (wl[h] * RS32);
                kv = row[256 + h * HD + d];
                vv = row[512 + h * HD + d];
            } else if (d < DIMT) {
                int e = d - HD;
                float cc = c3[e % 3];
                qv = (row[768 + h * PDIM + e] + cc) * wc[h];
                kv = row[864 + h * PDIM + e] + cc;
                vv = row[960 + h * PDIM + e] + cc;
            }
            q2[u] = qv; k2[u] = kv; v2[u] = vv;
        }
        int bh = b * HN + h;
        size_t o = ((size_t)bh * NSEQ + pos) * 64 + d0;
        __nv_bfloat162 qh2 = __floats2bfloat162_rn(q2[0], q2[1]);
        __nv_bfloat162 kh2 = __floats2bfloat162_rn(k2[0], k2[1]);
        __nv_bfloat162 vh2 = __floats2bfloat162_rn(v2[0], v2[1]);
        __nv_bfloat162 ql2 = __floats2bfloat162_rn(q2[0] - __bfloat162float(qh2.x),
                                                   q2[1] - __bfloat162float(qh2.y));
        __nv_bfloat162 kl2 = __floats2bfloat162_rn(k2[0] - __bfloat162float(kh2.x),
                                                   k2[1] - __bfloat162float(kh2.y));
        __nv_bfloat162 vl2 = __floats2bfloat162_rn(v2[0] - __bfloat162float(vh2.x),
                                                   v2[1] - __bfloat162float(vh2.y));
        *(__nv_bfloat162*)(g_qh + o) = qh2;
        *(__nv_bfloat162*)(g_ql + o) = ql2;
        *(__nv_bfloat162*)(g_kh + o) = kh2;
        *(__nv_bfloat162*)(g_kl + o) = kl2;
        *(__nv_bfloat162*)(g_vh + o) = vh2;
        *(__nv_bfloat162*)(g_vl + o) = vl2;
    }
}

// ---------------- FA2 mma.sync flash attention (2-stage, ldsm4t V) ---------
#define BUF_SZ 28672
#define OFF_K  0
#define OFF_KL 7168
#define OFF_VT 14336
#define SB_RED 57344
#define SB_TOT 58368

template<bool MASKED>
__device__ __forceinline__ void attn_tile(
    u32 kls, u32 vth, u32 vtl, const float* __restrict__ kbj, u64 mb0, u64 mb1, int tig,
    const u32 (*__restrict__ qfh)[4], const u32 (*__restrict__ qfl)[4],
    float (*__restrict__ oc)[4], float& la, float& lb,
    float& m0a, float& m0b, bool init)
{
#pragma unroll
    for (int kj = 0; kj < 4; kj++) {
        const int nb0 = 2 * kj, nb1 = 2 * kj + 1;
        float sc0[4] = {0.f, 0.f, 0.f, 0.f};
        float sc1[4] = {0.f, 0.f, 0.f, 0.f};
#pragma unroll
        for (int ks = 0; ks < 3; ks++) {
            u32 a0, a1, a2, a3;
            ldsm4(a0, a1, a2, a3, kls + nb0 * 896 + ks * 32);
            mma16816(sc0, qfh[ks], a0, a1);
            mma16816(sc0, qfh[ks], a2, a3);
            mma16816(sc0, qfl[ks], a0, a1);
            u32 b0, b1, b2, b3;
            ldsm4(b0, b1, b2, b3, kls + nb1 * 896 + ks * 32);
            mma16816(sc1, qfh[ks], b0, b1);
            mma16816(sc1, qfh[ks], b2, b3);
            mma16816(sc1, qfl[ks], b0, b1);
        }
        {
            float2 kba = *(const float2*)(kbj + nb0 * 8 + 2 * tig);
            float2 kbb = *(const float2*)(kbj + nb1 * 8 + 2 * tig);
            sc0[0] += kba.x; sc0[1] += kba.y; sc0[2] += kba.x; sc0[3] += kba.y;
            sc1[0] += kbb.x; sc1[1] += kbb.y; sc1[2] += kbb.x; sc1[3] += kbb.y;
            if (MASKED) {
                int sh0 = nb0 * 8 + 2 * tig, sh1 = nb1 * 8 + 2 * tig;
                if ((mb0 >> sh0) & 1) sc0[0] = -INFINITY;
                if ((mb0 >> (sh0 + 1)) & 1) sc0[1] = -INFINITY;
                if ((mb1 >> sh0) & 1) sc0[2] = -INFINITY;
                if ((mb1 >> (sh0 + 1)) & 1) sc0[3] = -INFINITY;
                if ((mb0 >> sh1) & 1) sc1[0] = -INFINITY;
                if ((mb0 >> (sh1 + 1)) & 1) sc1[1] = -INFINITY;
                if ((mb1 >> sh1) & 1) sc1[2] = -INFINITY;
                if ((mb1 >> (sh1 + 1)) & 1) sc1[3] = -INFINITY;
            }
        }
        if (init && kj == 0) {
            float ma = fmaxf(fmaxf(sc0[0], sc0[1]), fmaxf(sc1[0], sc1[1]));
            float mb = fmaxf(fmaxf(sc0[2], sc0[3]), fmaxf(sc1[2], sc1[3]));
            ma = fmaxf(ma, __shfl_xor_sync(0xffffffffu, ma, 1));
            ma = fmaxf(ma, __shfl_xor_sync(0xffffffffu, ma, 2));
            mb = fmaxf(mb, __shfl_xor_sync(0xffffffffu, mb, 1));
            mb = fmaxf(mb, __shfl_xor_sync(0xffffffffu, mb, 2));
            m0a = fmaxf(ma, -1e4f) + 2.f;
            m0b = fmaxf(mb, -1e4f) + 2.f;
        }
        float p0 = __expf(sc0[0] - m0a), p1 = __expf(sc0[1] - m0a);
        float p2 = __expf(sc0[2] - m0b), p3 = __expf(sc0[3] - m0b);
        float p4 = __expf(sc1[0] - m0a), p5 = __expf(sc1[1] - m0a);
        float p6 = __expf(sc1[2] - m0b), p7 = __expf(sc1[3] - m0b);
        la += (p0 + p1) + (p4 + p5);
        lb += (p2 + p3) + (p6 + p7);
        u32 u0 = __float_as_uint(p0), u1 = __float_as_uint(p1);
        u32 u2 = __float_as_uint(p2), u3 = __float_as_uint(p3);
        u32 u4 = __float_as_uint(p4), u5 = __float_as_uint(p5);
        u32 u6 = __float_as_uint(p6), u7 = __float_as_uint(p7);
        u32 pha[4], pla[4];
        pha[0] = __byte_perm(u0, u1, 0x7632);
        pha[1] = __byte_perm(u2, u3, 0x7632);
        pha[2] = __byte_perm(u4, u5, 0x7632);
        pha[3] = __byte_perm(u6, u7, 0x7632);
        pla[0] = pkb(p0 - __uint_as_float(u0 & 0xFFFF0000u), p1 - __uint_as_float(u1 & 0xFFFF0000u));
        pla[1] = pkb(p2 - __uint_as_float(u2 & 0xFFFF0000u), p3 - __uint_as_float(u3 & 0xFFFF0000u));
        pla[2] = pkb(p4 - __uint_as_float(u4 & 0xFFFF0000u), p5 - __uint_as_float(u5 & 0xFFFF0000u));
        pla[3] = pkb(p6 - __uint_as_float(u6 & 0xFFFF0000u), p7 - __uint_as_float(u7 & 0xFFFF0000u));
#pragma unroll
        for (int ctp = 0; ctp < 3; ctp++) {
            u32 vh0, vh1, vh2, vh3, vl0, vl1, vl2, vl3;
            ldsm4t(vh0, vh1, vh2, vh3, vth + kj * 1792 + ctp * 32);
            ldsm4t(vl0, vl1, vl2, vl3, vtl + kj * 1792 + ctp * 32);
            mma16816(oc[2 * ctp], pha, vh0, vh1);
            mma16816(oc[2 * ctp], pha, vl0, vl1);
            mma16816(oc[2 * ctp], pla, vh0, vh1);
            mma16816(oc[2 * ctp + 1], pha, vh2, vh3);
            mma16816(oc[2 * ctp + 1], pha, vl2, vl3);
            mma16816(oc[2 * ctp + 1], pla, vh2, vh3);
        }
    }
}

__global__ __launch_bounds__(256, 2)
void attn_kernel(float* __restrict__ ctx) {
    extern __shared__ char smem[];
    const u32 sb = smem_u32(smem);
    const int t = threadIdx.x;
    const int w = t >> 5, lane = t & 31;
    const int gid = lane >> 2, tig = lane & 3;
    const int rb = w * 16;
    const int i0 = blockIdx.x * 128, h = blockIdx.y, b = blockIdx.z;
    const int bh = b * HN + h;
    const float* kbg = g_kb + (size_t)bh * NSEQ;

    const int mid = lane >> 3, r8 = lane & 7;
    const u32 klbase = sb + ((mid < 2) ? OFF_K : OFF_KL) + r8 * 112 + (mid & 1) * 16;
    const u32 vtbase = sb + OFF_VT + (u32)(((mid & 1) * 8 + r8) * 112 + (mid >> 1) * 16);

#define KV_ISSUE(jn, nb_base) do {                                                                 \
        _Pragma("unroll")                                                                          \
        for (int rep = 0; rep < 3; rep++) {                                                        \
            int i = t + rep * 256;                                                                 \
            int arr = i / 384, rem = i % 384;                                                      \
            int row_ = rem / 6, ch = rem % 6;                                                      \
            size_t gb = ((size_t)bh * NSEQ + (jn) + row_) << 7;                                    \
            cp16((nb_base) + OFF_K + arr * 7168 + row_ * 112 + ch * 16,                            \
                 (const char*)(arr ? g_kl : g_kh) + gb + ch * 16);                                 \
            cp16((nb_base) + OFF_VT + arr * 7168 + row_ * 112 + ch * 16,                           \
                 (const char*)(arr ? g_vl : g_vh) + gb + ch * 16);                                 \
        }                                                                                          \
    } while (0)

    KV_ISSUE(0, sb);
    CP_COMMIT();

    {
        int arr = t >> 7, r = t & 127;
        const uint4* src = (const uint4*)((arr ? g_ql : g_qh) + ((size_t)bh * NSEQ + i0 + r) * 64);
        char* dst = smem + BUF_SZ + arr * 12288 + r * 96;
#pragma unroll
        for (int g = 0; g < 6; g++) *(uint4*)(dst + g * 16) = src[g];
    }
    __syncthreads();

    u32 qfh[3][4], qfl[3][4];
    {
        const char* Qb = smem + BUF_SZ;
#pragma unroll
        for (int ks = 0; ks < 3; ks++) {
            int co = ks * 32 + 4 * tig;
            int r0 = (rb + gid) * 96, r1 = (rb + gid + 8) * 96;
            qfh[ks][0] = *(const u32*)(Qb + r0 + co);
            qfh[ks][1] = *(const u32*)(Qb + r1 + co);
            qfh[ks][2] = *(const u32*)(Qb + r0 + co + 16);
            qfh[ks][3] = *(const u32*)(Qb + r1 + co + 16);
            qfl[ks][0] = *(const u32*)(Qb + 12288 + r0 + co);
            qfl[ks][1] = *(const u32*)(Qb + 12288 + r1 + co);
            qfl[ks][2] = *(const u32*)(Qb + 12288 + r0 + co + 16);
            qfl[ks][3] = *(const u32*)(Qb + 12288 + r1 + co + 16);
        }
    }

    float oc[6][4];
#pragma unroll
    for (int ct = 0; ct < 6; ct++)
#pragma unroll
        for (int i = 0; i < 4; i++) oc[ct][i] = 0.f;

    float la = 0.f, lb = 0.f, m0a = 0.f, m0b = 0.f;
    const u64* mb0p = g_mbits + ((size_t)(b * NSEQ + i0 + rb + gid)) * (NSEQ / 64);
    const u64* mb1p = mb0p + 8 * (NSEQ / 64);

    for (int tt = 0; tt < 32; tt++) {
        const int j0 = tt * 64;
        const u64 mb0 = mb0p[tt], mb1 = mb1p[tt];
        CP_WAIT0();
        __syncthreads();
        if (tt + 1 < 32) {
            KV_ISSUE(j0 + 64, sb + ((tt + 1) & 1) * BUF_SZ);
            CP_COMMIT();
        }
        const u32 kls = klbase + (tt & 1) * BUF_SZ;
        const u32 vth = vtbase + (tt & 1) * BUF_SZ;
        const u32 vtl = vth + 7168;

        if ((mb0 | mb1) == 0ull)
            attn_tile<false>(kls, vth, vtl, kbg + j0, mb0, mb1, tig, qfh, qfl,
                             oc, la, lb, m0a, m0b, tt == 0);
        else
            attn_tile<true>(kls, vth, vtl, kbg + j0, mb0, mb1, tig, qfh, qfl,
                            oc, la, lb, m0a, m0b, tt == 0);
    }

    // ---- epilogue ----
    la += __shfl_xor_sync(0xffffffffu, la, 1);
    la += __shfl_xor_sync(0xffffffffu, la, 2);
    lb += __shfl_xor_sync(0xffffffffu, lb, 1);
    lb += __shfl_xor_sync(0xffffffffu, lb, 2);
    float* red = (float*)(smem + SB_RED);
    float* Es = (float*)smem;
#pragma unroll
    for (int ct = 0; ct < 6; ct++) {
        *(float2*)&Es[(rb + gid) * 50 + ct * 8 + 2 * tig] = make_float2(oc[ct][0], oc[ct][1]);
        *(float2*)&Es[(rb + gid + 8) * 50 + ct * 8 + 2 * tig] = make_float2(oc[ct][2], oc[ct][3]);
    }
    if (tig == 0) { red[rb + gid] = la; red[rb + gid + 8] = lb; }
    __syncthreads();

    int row = t >> 1, half = t & 1;
    float inv = 1.f / red[row];
    size_t ob = ((size_t)b * NSEQ + i0 + row) * CTXW;
    const float* orow = Es + row * 50;
    const int cbeg = half ? 24 : 0, cend = half ? 44 : 24;
    for (int c = cbeg; c < cend; c++) {
        float o = orow[c] * inv;
        if (c < HD) ctx[ob + h * HD + c] = o;
        else        ctx[ob + 256 + h * PDIM + (c - HD)] = o;
    }
#undef KV_ISSUE
}

// ---------------------------------------------------------------------------
extern "C" void kernel_launch(void* const* d_in, const int* in_sizes, int n_in,
                              void* d_out, int out_size) {
    const float* feat = (const float*)d_in[0];
    const float* coords = (const float*)d_in[1];
    const unsigned char* mask = (const unsigned char*)d_in[2];
    const float* Wo = (const float*)d_in[15];
    const float* bo = (const float*)d_in[16];
    float* out = (float*)d_out;

    void* p;
    cudaGetSymbolAddress(&p, g_praw); float* praw = (float*)p;
    cudaGetSymbolAddress(&p, g_ctx);  float* ctx = (float*)p;

    const int M = BSZ * NSEQ;
    ProjArgs pa;
    pa.W[0] = (const float*)d_in[3];  pa.bias[0] = (const float*)d_in[4];
    pa.W[1] = (const float*)d_in[5];  pa.bias[1] = (const float*)d_in[6];
    pa.W[2] = (const float*)d_in[7];  pa.bias[2] = (const float*)d_in[8];
    pa.W[3] = (const float*)d_in[9];  pa.bias[3] = (const float*)d_in[10];
    pa.W[4] = (const float*)d_in[11]; pa.bias[4] = (const float*)d_in[12];
    pa.W[5] = (const float*)d_in[13]; pa.bias[5] = (const float*)d_in[14];
    proj_kernel<<<dim3(18, M / 64), 256>>>(feat, pa, praw);

    pack_mask<<<(BSZ * NSEQ * (NSEQ / 64) + 255) / 256, 256>>>(mask);
    transform_kernel<<<M, 128>>>(coords, (const float*)d_in[17], (const float*)d_in[18]);

    cudaFuncSetAttribute(attn_kernel, cudaFuncAttributeMaxDynamicSharedMemorySize, SB_TOT);
    attn_kernel<<<dim3(16, HN, BSZ), 256, SB_TOT>>>(ctx);

    gemm_kernel<<<dim3(4, M / 64), 256>>>(ctx, Wo, bo, out, CTXW, 256, 256);
}